// round 1
// baseline (speedup 1.0000x reference)
#include <cuda_runtime.h>

// KVQuantizerDequantizer: asymmetric 4-bit RTN quantize + dequantize,
// groupsize 128 along last dim. Input (4,32,4096,128) fp32 -> same shape fp32.
// One warp handles one group of 128 floats (each lane: float4 = 4 elems).

#define MAXQ 15.0f
#define EPS 1e-8f

__global__ void __launch_bounds__(256, 8)
kvq_kernel(const float* __restrict__ x, float* __restrict__ out, long long n_groups) {
    // warp id across the grid
    long long warp_global = (long long)blockIdx.x * (blockDim.x >> 5) + (threadIdx.x >> 5);
    if (warp_global >= n_groups) return;
    int lane = threadIdx.x & 31;

    const float4* xg = reinterpret_cast<const float4*>(x + warp_global * 128);
    float4 v = xg[lane];

    // per-thread min/max over 4 values
    float mn = fminf(fminf(v.x, v.y), fminf(v.z, v.w));
    float mx = fmaxf(fmaxf(v.x, v.y), fmaxf(v.z, v.w));

    // warp butterfly reduction
    #pragma unroll
    for (int off = 16; off > 0; off >>= 1) {
        mn = fminf(mn, __shfl_xor_sync(0xffffffffu, mn, off));
        mx = fmaxf(mx, __shfl_xor_sync(0xffffffffu, mx, off));
    }

    // scale / offset (CLIP_RATIO = 1.0)
    float scale = fmaxf((mx - mn) / MAXQ, EPS);
    float offset = rintf(-mn / scale);

    // quantize + dequantize (round half to even == jnp.round == rintf under RN)
    float4 r;
    {
        float q;
        q = fminf(fmaxf(rintf(v.x / scale) + offset, 0.0f), MAXQ); r.x = (q - offset) * scale;
        q = fminf(fmaxf(rintf(v.y / scale) + offset, 0.0f), MAXQ); r.y = (q - offset) * scale;
        q = fminf(fmaxf(rintf(v.z / scale) + offset, 0.0f), MAXQ); r.z = (q - offset) * scale;
        q = fminf(fmaxf(rintf(v.w / scale) + offset, 0.0f), MAXQ); r.w = (q - offset) * scale;
    }

    float4* og = reinterpret_cast<float4*>(out + warp_global * 128);
    og[lane] = r;
}

extern "C" void kernel_launch(void* const* d_in, const int* in_sizes, int n_in,
                              void* d_out, int out_size) {
    const float* x = (const float*)d_in[0];
    float* out = (float*)d_out;

    long long n = (long long)in_sizes[0];      // total elements
    long long n_groups = n / 128;              // 524288 for the given shape

    const int threads = 256;                   // 8 warps = 8 groups per block
    long long warps_per_block = threads / 32;
    long long blocks = (n_groups + warps_per_block - 1) / warps_per_block;

    kvq_kernel<<<(unsigned)blocks, threads>>>(x, out, n_groups);
}

// round 2
// speedup vs baseline: 1.1546x; 1.1546x over previous
#include <cuda_runtime.h>

// KVQuantizerDequantizer: asymmetric 4-bit RTN quantize+dequantize, groups of
// 128 floats along last dim. 8 lanes per group, 4 groups per warp:
//  - each thread loads 4 independent float4 (16 floats) -> MLP_p1 = 4
//  - min/max reduction: 15 local ops + 3 butterfly shuffle steps (xor 1,2,4)
//  - one fp32 division per thread (reciprocal of scale), multiplies elsewhere

#define MAXQ 15.0f
#define EPS 1e-8f

__global__ void __launch_bounds__(256)
kvq_kernel(const float* __restrict__ x, float* __restrict__ out, long long n_groups) {
    const int lane = threadIdx.x & 31;
    const int sl   = lane & 7;          // lane within 8-lane sub-group
    const long long warp_global = (long long)blockIdx.x * (blockDim.x >> 5) + (threadIdx.x >> 5);
    const long long group = warp_global * 4 + (lane >> 3);
    if (group >= n_groups) return;

    const float4* gp = reinterpret_cast<const float4*>(x + group * 128);

    // 4 independent loads, issued back-to-back (MLP=4)
    float4 a = gp[sl];
    float4 b = gp[sl + 8];
    float4 c = gp[sl + 16];
    float4 d = gp[sl + 24];

    // local min/max over 16 values
    float mn = fminf(fminf(fminf(a.x, a.y), fminf(a.z, a.w)),
                     fminf(fminf(b.x, b.y), fminf(b.z, b.w)));
    mn = fminf(mn, fminf(fminf(fminf(c.x, c.y), fminf(c.z, c.w)),
                         fminf(fminf(d.x, d.y), fminf(d.z, d.w))));
    float mx = fmaxf(fmaxf(fmaxf(a.x, a.y), fmaxf(a.z, a.w)),
                     fmaxf(fmaxf(b.x, b.y), fmaxf(b.z, b.w)));
    mx = fmaxf(mx, fmaxf(fmaxf(fmaxf(c.x, c.y), fmaxf(c.z, c.w)),
                         fmaxf(fmaxf(d.x, d.y), fmaxf(d.z, d.w))));

    // butterfly within the 8-lane sub-group (xor 1,2,4 never leaves the octet)
    #pragma unroll
    for (int off = 1; off < 8; off <<= 1) {
        mn = fminf(mn, __shfl_xor_sync(0xffffffffu, mn, off));
        mx = fmaxf(mx, __shfl_xor_sync(0xffffffffu, mx, off));
    }

    // scale / offset (CLIP_RATIO = 1.0); one true division per thread
    const float scale  = fmaxf((mx - mn) / MAXQ, EPS);
    const float rscale = 1.0f / scale;
    const float offset = rintf(-mn * rscale);

    // quantize + dequantize
    #define QDQ(e) do { \
        float q = fminf(fmaxf(rintf((e) * rscale) + offset, 0.0f), MAXQ); \
        (e) = (q - offset) * scale; \
    } while (0)
    QDQ(a.x); QDQ(a.y); QDQ(a.z); QDQ(a.w);
    QDQ(b.x); QDQ(b.y); QDQ(b.z); QDQ(b.w);
    QDQ(c.x); QDQ(c.y); QDQ(c.z); QDQ(c.w);
    QDQ(d.x); QDQ(d.y); QDQ(d.z); QDQ(d.w);
    #undef QDQ

    float4* og = reinterpret_cast<float4*>(out + group * 128);
    og[sl]      = a;
    og[sl + 8]  = b;
    og[sl + 16] = c;
    og[sl + 24] = d;
}

extern "C" void kernel_launch(void* const* d_in, const int* in_sizes, int n_in,
                              void* d_out, int out_size) {
    const float* x = (const float*)d_in[0];
    float* out = (float*)d_out;

    long long n = (long long)in_sizes[0];
    long long n_groups = n / 128;              // 524288

    const int threads = 256;                   // 8 warps -> 32 groups per block
    long long groups_per_block = (threads / 32) * 4;
    long long blocks = (n_groups + groups_per_block - 1) / groups_per_block;

    kvq_kernel<<<(unsigned)blocks, threads>>>(x, out, n_groups);
}

// round 3
// speedup vs baseline: 1.1550x; 1.0004x over previous
#include <cuda_runtime.h>

// KVQuantizerDequantizer: asymmetric 4-bit RTN quantize+dequantize, groups of
// 128 floats along last dim.
// Layout: 4 lanes per group, 8 groups per warp. Each thread loads 8
// independent float4 (32 floats = 1/4 group) front-batched -> MLP_p1 = 8.
// Reduction: 31 local min/max ops + 2 butterfly shuffle steps (xor 1,2).

#define MAXQ 15.0f
#define EPS 1e-8f

__global__ void __launch_bounds__(256)
kvq_kernel(const float* __restrict__ x, float* __restrict__ out, long long n_groups) {
    const int lane = threadIdx.x & 31;
    const int sl   = lane & 3;                      // lane within 4-lane quad
    const long long warp_global = (long long)blockIdx.x * (blockDim.x >> 5) + (threadIdx.x >> 5);
    const long long group = warp_global * 8 + (lane >> 2);
    if (group >= n_groups) return;

    const float4* gp = reinterpret_cast<const float4*>(x + group * 128);

    // 8 independent loads, front-batched (MLP=8). Load i covers bytes
    // [64*i, 64*i+64) of the group across the quad.
    float4 v0 = __ldcs(&gp[sl]);
    float4 v1 = __ldcs(&gp[sl + 4]);
    float4 v2 = __ldcs(&gp[sl + 8]);
    float4 v3 = __ldcs(&gp[sl + 12]);
    float4 v4 = __ldcs(&gp[sl + 16]);
    float4 v5 = __ldcs(&gp[sl + 20]);
    float4 v6 = __ldcs(&gp[sl + 24]);
    float4 v7 = __ldcs(&gp[sl + 28]);

    // local min/max over 32 values
    #define MN4(v) fminf(fminf((v).x, (v).y), fminf((v).z, (v).w))
    #define MX4(v) fmaxf(fmaxf((v).x, (v).y), fmaxf((v).z, (v).w))
    float mn = fminf(fminf(fminf(MN4(v0), MN4(v1)), fminf(MN4(v2), MN4(v3))),
                     fminf(fminf(MN4(v4), MN4(v5)), fminf(MN4(v6), MN4(v7))));
    float mx = fmaxf(fmaxf(fmaxf(MX4(v0), MX4(v1)), fmaxf(MX4(v2), MX4(v3))),
                     fmaxf(fmaxf(MX4(v4), MX4(v5)), fmaxf(MX4(v6), MX4(v7))));
    #undef MN4
    #undef MX4

    // butterfly within the 4-lane quad (xor 1,2 never leaves the quad)
    mn = fminf(mn, __shfl_xor_sync(0xffffffffu, mn, 1));
    mx = fmaxf(mx, __shfl_xor_sync(0xffffffffu, mx, 1));
    mn = fminf(mn, __shfl_xor_sync(0xffffffffu, mn, 2));
    mx = fmaxf(mx, __shfl_xor_sync(0xffffffffu, mx, 2));

    // scale / offset (CLIP_RATIO = 1.0); one true division per thread
    const float scale  = fmaxf((mx - mn) / MAXQ, EPS);
    const float rscale = 1.0f / scale;
    const float offset = rintf(-mn * rscale);

    // quantize + dequantize
    #define QDQ(e) do { \
        float q = fminf(fmaxf(rintf((e) * rscale) + offset, 0.0f), MAXQ); \
        (e) = (q - offset) * scale; \
    } while (0)
    #define QDQ4(v) do { QDQ((v).x); QDQ((v).y); QDQ((v).z); QDQ((v).w); } while (0)
    QDQ4(v0); QDQ4(v1); QDQ4(v2); QDQ4(v3);
    QDQ4(v4); QDQ4(v5); QDQ4(v6); QDQ4(v7);
    #undef QDQ4
    #undef QDQ

    float4* og = reinterpret_cast<float4*>(out + group * 128);
    __stcs(&og[sl],      v0);
    __stcs(&og[sl + 4],  v1);
    __stcs(&og[sl + 8],  v2);
    __stcs(&og[sl + 12], v3);
    __stcs(&og[sl + 16], v4);
    __stcs(&og[sl + 20], v5);
    __stcs(&og[sl + 24], v6);
    __stcs(&og[sl + 28], v7);
}

extern "C" void kernel_launch(void* const* d_in, const int* in_sizes, int n_in,
                              void* d_out, int out_size) {
    const float* x = (const float*)d_in[0];
    float* out = (float*)d_out;

    long long n = (long long)in_sizes[0];
    long long n_groups = n / 128;              // 524288

    const int threads = 256;                   // 8 warps -> 64 groups per block
    long long groups_per_block = (threads / 32) * 8;
    long long blocks = (n_groups + groups_per_block - 1) / groups_per_block;

    kvq_kernel<<<(unsigned)blocks, threads>>>(x, out, n_groups);
}